// round 8
// baseline (speedup 1.0000x reference)
#include <cuda_runtime.h>

#define NUM_CLASSES 1000
#define BATCH 8192
#define DD 4096
#define DENSE_BLOCKS NUM_CLASSES            // one block per class
#define CE_BLOCKS   (BATCH / 32)            // 32 warps/block, 1 row/warp = 256
#define TOTAL_BLOCKS (DENSE_BLOCKS + CE_BLOCKS)
#define MAX_PER_CLASS 512                   // binomial(8192,1e-3): mean 8.2, max ~25

// ---- graph-safe scratch (zero-init at load; reset by last block each run) ----
__device__ double g_loss1;
__device__ double g_loss2;
__device__ unsigned int g_done;

__device__ __forceinline__ float tanh_fast(float x) {
    float y;
    asm("tanh.approx.f32 %0, %1;" : "=f"(y) : "f"(x));
    return y;
}

__device__ __forceinline__ void sig_bce(float x, float y, float& sig, float& bce) {
    const float t  = tanh_fast(0.5f * x);
    sig = fmaf(0.5f, t, 0.5f);                         // sigmoid(x)
    const float sp = fmaf(0.5f, fabsf(t), 0.5f);       // sigmoid(|x|)
    bce = fmaxf(x, 0.f) - x * y - __logf(sp);          // stable BCE w/ logits
}

// ---------------------------------------------------------------------------
// Single fused kernel.
//   blocks [0, 1000)      : dense segment-sum + BCE, one class per block
//   blocks [1000, 1256)   : cross-entropy, one row per warp
// Last block to finish combines losses into out[0] and resets scratch.
// ---------------------------------------------------------------------------
__global__ __launch_bounds__(1024, 1) void main_kernel(
        const float* __restrict__ logits,
        const int*   __restrict__ target,
        const float* __restrict__ dense_out,
        const float* __restrict__ dense_labels,
        float* __restrict__ out) {

    float* out_ds = out + 1;                               // [1000,4096]
    float* out_ta = out + 1 + (size_t)NUM_CLASSES * DD;    // [1000]

    const int tid = threadIdx.x;

    if (blockIdx.x < DENSE_BLOCKS) {
        // =================== DENSE SEGSUM + BCE (class c) ===================
        const int c = blockIdx.x;

        // label row for this class: one float4 per thread
        const float4 y = ((const float4*)(dense_labels + (size_t)c * DD))[tid];

        // find this class's rows by scanning targets (L2-resident, 8 per thread)
        __shared__ int s_cnt;
        __shared__ int s_rows[MAX_PER_CLASS];
        if (tid == 0) s_cnt = 0;
        __syncthreads();
        #pragma unroll
        for (int k = 0; k < BATCH / 1024; ++k) {
            const int i = tid + k * 1024;
            if (target[i] == c) {
                const int p = atomicAdd(&s_cnt, 1);
                if (p < MAX_PER_CLASS) s_rows[p] = i;
            }
        }
        __syncthreads();
        const int n = s_cnt;
        if (tid == 0) out_ta[c] = (float)n;

        float4 acc = make_float4(0.f, 0.f, 0.f, 0.f);
        float  lsum = 0.f;

        int i = 0;
        for (; i + 2 <= n; i += 2) {                       // MLP=2 on row streams
            const int r0 = s_rows[i];
            const int r1 = s_rows[i + 1];
            const float4 x0 = ((const float4*)(dense_out + (size_t)r0 * DD))[tid];
            const float4 x1 = ((const float4*)(dense_out + (size_t)r1 * DD))[tid];
            float sg, bc;
            sig_bce(x0.x, y.x, sg, bc); acc.x += sg; lsum += bc;
            sig_bce(x0.y, y.y, sg, bc); acc.y += sg; lsum += bc;
            sig_bce(x0.z, y.z, sg, bc); acc.z += sg; lsum += bc;
            sig_bce(x0.w, y.w, sg, bc); acc.w += sg; lsum += bc;
            sig_bce(x1.x, y.x, sg, bc); acc.x += sg; lsum += bc;
            sig_bce(x1.y, y.y, sg, bc); acc.y += sg; lsum += bc;
            sig_bce(x1.z, y.z, sg, bc); acc.z += sg; lsum += bc;
            sig_bce(x1.w, y.w, sg, bc); acc.w += sg; lsum += bc;
        }
        if (i < n) {
            const int r0 = s_rows[i];
            const float4 x0 = ((const float4*)(dense_out + (size_t)r0 * DD))[tid];
            float sg, bc;
            sig_bce(x0.x, y.x, sg, bc); acc.x += sg; lsum += bc;
            sig_bce(x0.y, y.y, sg, bc); acc.y += sg; lsum += bc;
            sig_bce(x0.z, y.z, sg, bc); acc.z += sg; lsum += bc;
            sig_bce(x0.w, y.w, sg, bc); acc.w += sg; lsum += bc;
        }

        // out_ds is offset by +1 float from out -> only 4B-aligned: scalar stores
        float* dst = out_ds + (size_t)c * DD + (size_t)tid * 4;
        dst[0] = acc.x; dst[1] = acc.y; dst[2] = acc.z; dst[3] = acc.w;

        // block-reduce BCE partial
        #pragma unroll
        for (int o = 16; o; o >>= 1)
            lsum += __shfl_xor_sync(0xffffffffu, lsum, o);
        __shared__ float wpart[32];
        const int wid = tid >> 5, lane = tid & 31;
        if (lane == 0) wpart[wid] = lsum;
        __syncthreads();
        if (tid == 0) {
            float bs = 0.f;
            #pragma unroll
            for (int w = 0; w < 32; ++w) bs += wpart[w];
            atomicAdd(&g_loss2, (double)bs);
        }

    } else {
        // ========================= CROSS-ENTROPY ===========================
        const int warp = tid >> 5;
        const int lane = tid & 31;
        const int r    = (blockIdx.x - DENSE_BLOCKS) * 32 + warp;
        const float4* row = (const float4*)(logits + (size_t)r * NUM_CLASSES);

        float m = -1e30f, ssum = 0.f;
        #pragma unroll
        for (int k = 0; k < 8; ++k) {
            const int idx = k * 32 + lane;           // float4 index, 250 valid
            if (idx < NUM_CLASSES / 4) {
                const float4 v = row[idx];
                const float mv = fmaxf(fmaxf(v.x, v.y), fmaxf(v.z, v.w));
                const float mn = fmaxf(m, mv);
                ssum = ssum * __expf(m - mn)
                     + __expf(v.x - mn) + __expf(v.y - mn)
                     + __expf(v.z - mn) + __expf(v.w - mn);
                m = mn;
            }
        }
        #pragma unroll
        for (int off = 16; off; off >>= 1) {
            const float mo = __shfl_xor_sync(0xffffffffu, m, off);
            const float so = __shfl_xor_sync(0xffffffffu, ssum, off);
            const float mn = fmaxf(m, mo);
            ssum = ssum * __expf(m - mn) + so * __expf(mo - mn);
            m = mn;
        }

        __shared__ float part[32];
        if (lane == 0)
            part[warp] = (__logf(ssum) + m)
                       - logits[(size_t)r * NUM_CLASSES + target[r]];
        __syncthreads();
        if (tid == 0) {
            float bs = 0.f;
            #pragma unroll
            for (int w = 0; w < 32; ++w) bs += part[w];
            atomicAdd(&g_loss1, (double)bs);
        }
    }

    // ----------------- last-block finalize (no extra launch) ----------------
    __syncthreads();
    if (tid == 0) {
        __threadfence();
        const unsigned int ticket = atomicAdd(&g_done, 1u);
        if (ticket == TOTAL_BLOCKS - 1) {
            __threadfence();
            const double l1 = g_loss1 / (double)BATCH;
            const double l2 = g_loss2 / ((double)BATCH * (double)DD);
            out[0] = (float)(0.5 * l1 + 0.5 * l2);
            // reset scratch for the next graph replay
            g_loss1 = 0.0;
            g_loss2 = 0.0;
            g_done  = 0u;
        }
    }
}

// ---------------------------------------------------------------------------
extern "C" void kernel_launch(void* const* d_in, const int* in_sizes, int n_in,
                              void* d_out, int out_size) {
    const float* logits       = (const float*)d_in[0];
    const float* dense_out    = (const float*)d_in[1];
    const int*   target       = (const int*)  d_in[2];
    const float* dense_labels = (const float*)d_in[3];

    main_kernel<<<TOTAL_BLOCKS, 1024>>>(logits, target, dense_out,
                                        dense_labels, (float*)d_out);
}

// round 10
// speedup vs baseline: 1.6010x; 1.6010x over previous
#include <cuda_runtime.h>

#define NUM_CLASSES 1000
#define BATCH 8192
#define DD 4096
#define DENSE_BLOCKS 4000              // 1000 classes * 4 column chunks
#define CE_BLOCKS 1024                 // 8 rows per block (8 warps)
#define TOTAL_BLOCKS (DENSE_BLOCKS + CE_BLOCKS)

// ---- graph-safe scratch (loss/done reset in-kernel each replay) ----
__device__ double g_loss1;
__device__ double g_loss2;
__device__ unsigned int g_done;
__device__ int    g_offsets[NUM_CLASSES + 1];
__device__ int    g_sorted [BATCH];

__device__ __forceinline__ float tanh_fast(float x) {
    float y;
    asm("tanh.approx.f32 %0, %1;" : "=f"(y) : "f"(x));
    return y;
}

__device__ __forceinline__ void sig_bce(float x, float y, float& sig, float& bce) {
    const float t  = tanh_fast(0.5f * x);
    sig = fmaf(0.5f, t, 0.5f);                         // sigmoid(x)
    const float sp = fmaf(0.5f, fabsf(t), 0.5f);       // sigmoid(|x|)
    bce = fmaxf(x, 0.f) - x * y - __logf(sp);          // stable BCE w/ logits
}

// ---------------------------------------------------------------------------
// K1: prep — histogram + warp-shuffle scan + counting-sort scatter, 1 block.
// Targets cached in registers; only 4 block barriers total.
// ---------------------------------------------------------------------------
__global__ __launch_bounds__(1024) void prep_kernel(const int* __restrict__ target,
                                                    float* __restrict__ out_ta) {
    __shared__ int hist[1024];
    __shared__ int wsum[32];
    const int tid  = threadIdx.x;
    const int lane = tid & 31, wid = tid >> 5;

    hist[tid] = 0;
    __syncthreads();

    int t[8];
    #pragma unroll
    for (int k = 0; k < 8; ++k) {
        t[k] = target[tid + k * 1024];
        atomicAdd(&hist[t[k]], 1);
    }
    __syncthreads();

    const int c = hist[tid];                    // count of bin tid
    if (tid < NUM_CLASSES) out_ta[tid] = (float)c;

    // inclusive scan: warp shuffle + one warp over warp sums
    int isc = c;
    #pragma unroll
    for (int o = 1; o < 32; o <<= 1) {
        const int v = __shfl_up_sync(0xffffffffu, isc, o);
        if (lane >= o) isc += v;
    }
    if (lane == 31) wsum[wid] = isc;
    __syncthreads();
    if (wid == 0) {
        int ws = wsum[lane];
        #pragma unroll
        for (int o = 1; o < 32; o <<= 1) {
            const int v = __shfl_up_sync(0xffffffffu, ws, o);
            if (lane >= o) ws += v;
        }
        wsum[lane] = ws;
    }
    __syncthreads();
    const int incl = isc + (wid ? wsum[wid - 1] : 0);
    const int excl = incl - c;

    if (tid < NUM_CLASSES) g_offsets[tid + 1] = incl;
    if (tid == 0) { g_offsets[0] = 0; g_loss1 = 0.0; g_loss2 = 0.0; g_done = 0u; }

    hist[tid] = excl;                           // reuse as cursor
    __syncthreads();

    #pragma unroll
    for (int k = 0; k < 8; ++k) {
        const int p = atomicAdd(&hist[t[k]], 1);
        g_sorted[p] = tid + k * 1024;           // order within class irrelevant
    }
}

// ---------------------------------------------------------------------------
// K2: fused main — dense segsum+BCE (blocks 0..3999) + CE (blocks 4000..5023).
// Last finishing block combines losses into out[0] (no extra launch).
// ---------------------------------------------------------------------------
__global__ __launch_bounds__(256) void main_kernel(
        const float* __restrict__ logits,
        const int*   __restrict__ target,
        const float* __restrict__ dense_out,
        const float* __restrict__ dense_labels,
        float* __restrict__ out) {

    float* out_ds = out + 1;                               // [1000,4096]

    if (blockIdx.x < DENSE_BLOCKS) {
        // ================= DENSE SEGSUM + BCE =================
        const int b    = blockIdx.x;
        const int c    = b >> 2;
        const int col4 = (b & 3) * 256 + threadIdx.x;      // float4 idx 0..1023

        const float4 y = ((const float4*)(dense_labels + (size_t)c * DD))[col4];

        const int s = g_offsets[c];
        const int e = g_offsets[c + 1];

        float4 acc = make_float4(0.f, 0.f, 0.f, 0.f);
        float  lsum = 0.f;
        float  sg, bc;

        int i = s;
        for (; i + 4 <= e; i += 4) {                       // MLP=4 on row loads
            const int r0 = __ldg(&g_sorted[i]);
            const int r1 = __ldg(&g_sorted[i + 1]);
            const int r2 = __ldg(&g_sorted[i + 2]);
            const int r3 = __ldg(&g_sorted[i + 3]);
            const float4 x0 = ((const float4*)(dense_out + (size_t)r0 * DD))[col4];
            const float4 x1 = ((const float4*)(dense_out + (size_t)r1 * DD))[col4];
            const float4 x2 = ((const float4*)(dense_out + (size_t)r2 * DD))[col4];
            const float4 x3 = ((const float4*)(dense_out + (size_t)r3 * DD))[col4];
            sig_bce(x0.x, y.x, sg, bc); acc.x += sg; lsum += bc;
            sig_bce(x0.y, y.y, sg, bc); acc.y += sg; lsum += bc;
            sig_bce(x0.z, y.z, sg, bc); acc.z += sg; lsum += bc;
            sig_bce(x0.w, y.w, sg, bc); acc.w += sg; lsum += bc;
            sig_bce(x1.x, y.x, sg, bc); acc.x += sg; lsum += bc;
            sig_bce(x1.y, y.y, sg, bc); acc.y += sg; lsum += bc;
            sig_bce(x1.z, y.z, sg, bc); acc.z += sg; lsum += bc;
            sig_bce(x1.w, y.w, sg, bc); acc.w += sg; lsum += bc;
            sig_bce(x2.x, y.x, sg, bc); acc.x += sg; lsum += bc;
            sig_bce(x2.y, y.y, sg, bc); acc.y += sg; lsum += bc;
            sig_bce(x2.z, y.z, sg, bc); acc.z += sg; lsum += bc;
            sig_bce(x2.w, y.w, sg, bc); acc.w += sg; lsum += bc;
            sig_bce(x3.x, y.x, sg, bc); acc.x += sg; lsum += bc;
            sig_bce(x3.y, y.y, sg, bc); acc.y += sg; lsum += bc;
            sig_bce(x3.z, y.z, sg, bc); acc.z += sg; lsum += bc;
            sig_bce(x3.w, y.w, sg, bc); acc.w += sg; lsum += bc;
        }
        for (; i < e; ++i) {
            const int r0 = __ldg(&g_sorted[i]);
            const float4 x0 = ((const float4*)(dense_out + (size_t)r0 * DD))[col4];
            sig_bce(x0.x, y.x, sg, bc); acc.x += sg; lsum += bc;
            sig_bce(x0.y, y.y, sg, bc); acc.y += sg; lsum += bc;
            sig_bce(x0.z, y.z, sg, bc); acc.z += sg; lsum += bc;
            sig_bce(x0.w, y.w, sg, bc); acc.w += sg; lsum += bc;
        }

        float* dst = out_ds + (size_t)c * DD + (size_t)col4 * 4;  // 4B-aligned
        dst[0] = acc.x; dst[1] = acc.y; dst[2] = acc.z; dst[3] = acc.w;

        #pragma unroll
        for (int o = 16; o; o >>= 1)
            lsum += __shfl_xor_sync(0xffffffffu, lsum, o);
        __shared__ float wpart[8];
        const int wid = threadIdx.x >> 5, lane = threadIdx.x & 31;
        if (lane == 0) wpart[wid] = lsum;
        __syncthreads();
        if (threadIdx.x == 0) {
            float bs = 0.f;
            #pragma unroll
            for (int w = 0; w < 8; ++w) bs += wpart[w];
            atomicAdd(&g_loss2, (double)bs);
        }

    } else {
        // ==================== CROSS-ENTROPY ====================
        const int warp = threadIdx.x >> 5;
        const int lane = threadIdx.x & 31;
        const int r    = (blockIdx.x - DENSE_BLOCKS) * 8 + warp;
        const float4* row = (const float4*)(logits + (size_t)r * NUM_CLASSES);

        float m = -1e30f, ssum = 0.f;
        #pragma unroll
        for (int k = 0; k < 8; ++k) {
            const int idx = k * 32 + lane;           // float4 index, 250 valid
            if (idx < NUM_CLASSES / 4) {
                const float4 v = row[idx];
                const float mv = fmaxf(fmaxf(v.x, v.y), fmaxf(v.z, v.w));
                const float mn = fmaxf(m, mv);
                ssum = ssum * __expf(m - mn)
                     + __expf(v.x - mn) + __expf(v.y - mn)
                     + __expf(v.z - mn) + __expf(v.w - mn);
                m = mn;
            }
        }
        #pragma unroll
        for (int off = 16; off; off >>= 1) {
            const float mo = __shfl_xor_sync(0xffffffffu, m, off);
            const float so = __shfl_xor_sync(0xffffffffu, ssum, off);
            const float mn = fmaxf(m, mo);
            ssum = ssum * __expf(m - mn) + so * __expf(mo - mn);
            m = mn;
        }

        __shared__ float part[8];
        if (lane == 0)
            part[warp] = (__logf(ssum) + m)
                       - logits[(size_t)r * NUM_CLASSES + target[r]];
        __syncthreads();
        if (threadIdx.x == 0) {
            float bs = 0.f;
            #pragma unroll
            for (int w = 0; w < 8; ++w) bs += part[w];
            atomicAdd(&g_loss1, (double)bs);
        }
    }

    // --------------- last-block finalize (replaces final launch) ---------------
    if (threadIdx.x == 0) {
        __threadfence();
        const unsigned int ticket = atomicAdd(&g_done, 1u);
        if (ticket == TOTAL_BLOCKS - 1) {
            __threadfence();
            const double l1 = g_loss1 / (double)BATCH;
            const double l2 = g_loss2 / ((double)BATCH * (double)DD);
            out[0] = (float)(0.5 * l1 + 0.5 * l2);
            g_done = 0u;                    // reset for next graph replay
            g_loss1 = 0.0;                  // (prep also resets; belt & braces)
            g_loss2 = 0.0;
        }
    }
}

// ---------------------------------------------------------------------------
extern "C" void kernel_launch(void* const* d_in, const int* in_sizes, int n_in,
                              void* d_out, int out_size) {
    const float* logits       = (const float*)d_in[0];
    const float* dense_out    = (const float*)d_in[1];
    const int*   target       = (const int*)  d_in[2];
    const float* dense_labels = (const float*)d_in[3];

    float* out    = (float*)d_out;
    float* out_ta = out + 1 + (size_t)NUM_CLASSES * DD;

    prep_kernel<<<1, 1024>>>(target, out_ta);
    main_kernel<<<TOTAL_BLOCKS, 256>>>(logits, target, dense_out,
                                       dense_labels, out);
}

// round 11
// speedup vs baseline: 1.7247x; 1.0772x over previous
#include <cuda_runtime.h>

#define NUM_CLASSES 1000
#define BATCH 8192
#define DD 4096
#define DENSE_BLOCKS 4000              // 1000 classes * 4 column chunks
#define CE_BLOCKS 1024                 // 8 rows per block (8 warps)
#define TOTAL_BLOCKS (DENSE_BLOCKS + CE_BLOCKS)
#define SROWS 64                       // staged indices (P[n>64] ~ 0; guarded)

// ---- graph-safe scratch (loss/done reset in-kernel each replay) ----
__device__ double g_loss1;
__device__ double g_loss2;
__device__ unsigned int g_done;
__device__ int    g_offsets[NUM_CLASSES + 1];
__device__ int    g_sorted [BATCH];

__device__ __forceinline__ float tanh_fast(float x) {
    float y;
    asm("tanh.approx.f32 %0, %1;" : "=f"(y) : "f"(x));
    return y;
}

__device__ __forceinline__ void sig_bce(float x, float y, float& sig, float& bce) {
    const float t  = tanh_fast(0.5f * x);
    sig = fmaf(0.5f, t, 0.5f);                         // sigmoid(x)
    const float sp = fmaf(0.5f, fabsf(t), 0.5f);       // sigmoid(|x|)
    bce = fmaxf(x, 0.f) - x * y - __logf(sp);          // stable BCE w/ logits
}

__device__ __forceinline__ float4 ldcs4(const float4* p) {
    float4 v;
    asm("ld.global.cs.v4.f32 {%0,%1,%2,%3}, [%4];"
        : "=f"(v.x), "=f"(v.y), "=f"(v.z), "=f"(v.w) : "l"(p));
    return v;
}

__device__ __forceinline__ void stcs(float* p, float v) {
    asm volatile("st.global.cs.f32 [%0], %1;" :: "l"(p), "f"(v));
}

// ---------------------------------------------------------------------------
// K1: prep — histogram + warp-shuffle scan + counting-sort scatter, 1 block.
// ---------------------------------------------------------------------------
__global__ __launch_bounds__(1024) void prep_kernel(const int* __restrict__ target,
                                                    float* __restrict__ out_ta) {
    __shared__ int hist[1024];
    __shared__ int wsum[32];
    const int tid  = threadIdx.x;
    const int lane = tid & 31, wid = tid >> 5;

    hist[tid] = 0;
    __syncthreads();

    int t[8];
    #pragma unroll
    for (int k = 0; k < 8; ++k) {
        t[k] = target[tid + k * 1024];
        atomicAdd(&hist[t[k]], 1);
    }
    __syncthreads();

    const int c = hist[tid];
    if (tid < NUM_CLASSES) out_ta[tid] = (float)c;

    int isc = c;
    #pragma unroll
    for (int o = 1; o < 32; o <<= 1) {
        const int v = __shfl_up_sync(0xffffffffu, isc, o);
        if (lane >= o) isc += v;
    }
    if (lane == 31) wsum[wid] = isc;
    __syncthreads();
    if (wid == 0) {
        int ws = wsum[lane];
        #pragma unroll
        for (int o = 1; o < 32; o <<= 1) {
            const int v = __shfl_up_sync(0xffffffffu, ws, o);
            if (lane >= o) ws += v;
        }
        wsum[lane] = ws;
    }
    __syncthreads();
    const int incl = isc + (wid ? wsum[wid - 1] : 0);
    const int excl = incl - c;

    if (tid < NUM_CLASSES) g_offsets[tid + 1] = incl;
    if (tid == 0) { g_offsets[0] = 0; g_loss1 = 0.0; g_loss2 = 0.0; g_done = 0u; }

    hist[tid] = excl;                           // reuse as cursor
    __syncthreads();

    #pragma unroll
    for (int k = 0; k < 8; ++k) {
        const int p = atomicAdd(&hist[t[k]], 1);
        g_sorted[p] = tid + k * 1024;
    }
}

// ---------------------------------------------------------------------------
// K2: fused main — dense segsum+BCE (blocks 0..3999) + CE (blocks 4000..5023).
// ---------------------------------------------------------------------------
__global__ __launch_bounds__(256) void main_kernel(
        const float* __restrict__ logits,
        const int*   __restrict__ target,
        const float* __restrict__ dense_out,
        const float* __restrict__ dense_labels,
        float* __restrict__ out) {

    float* out_ds = out + 1;                               // [1000,4096]

    if (blockIdx.x < DENSE_BLOCKS) {
        // ================= DENSE SEGSUM + BCE =================
        const int b    = blockIdx.x;
        const int c    = b >> 2;
        const int col4 = (b & 3) * 256 + threadIdx.x;      // float4 idx 0..1023

        const float4 y = ((const float4*)(dense_labels + (size_t)c * DD))[col4];

        const int s = g_offsets[c];
        const int n = g_offsets[c + 1] - s;

        // stage indices in shared: removes L2 index load from the hot chain
        __shared__ int s_rows[SROWS];
        if (threadIdx.x < n && threadIdx.x < SROWS)
            s_rows[threadIdx.x] = g_sorted[s + threadIdx.x];
        __syncthreads();

        float4 acc = make_float4(0.f, 0.f, 0.f, 0.f);
        float  lsum = 0.f;
        float  sg, bc;

        int i = 0;
        for (; i + 4 <= n; i += 4) {                       // MLP=4 on row loads
            const int r0 = (i     < SROWS) ? s_rows[i]     : g_sorted[s + i];
            const int r1 = (i + 1 < SROWS) ? s_rows[i + 1] : g_sorted[s + i + 1];
            const int r2 = (i + 2 < SROWS) ? s_rows[i + 2] : g_sorted[s + i + 2];
            const int r3 = (i + 3 < SROWS) ? s_rows[i + 3] : g_sorted[s + i + 3];
            const float4 x0 = ldcs4((const float4*)(dense_out + (size_t)r0 * DD) + col4);
            const float4 x1 = ldcs4((const float4*)(dense_out + (size_t)r1 * DD) + col4);
            const float4 x2 = ldcs4((const float4*)(dense_out + (size_t)r2 * DD) + col4);
            const float4 x3 = ldcs4((const float4*)(dense_out + (size_t)r3 * DD) + col4);
            sig_bce(x0.x, y.x, sg, bc); acc.x += sg; lsum += bc;
            sig_bce(x0.y, y.y, sg, bc); acc.y += sg; lsum += bc;
            sig_bce(x0.z, y.z, sg, bc); acc.z += sg; lsum += bc;
            sig_bce(x0.w, y.w, sg, bc); acc.w += sg; lsum += bc;
            sig_bce(x1.x, y.x, sg, bc); acc.x += sg; lsum += bc;
            sig_bce(x1.y, y.y, sg, bc); acc.y += sg; lsum += bc;
            sig_bce(x1.z, y.z, sg, bc); acc.z += sg; lsum += bc;
            sig_bce(x1.w, y.w, sg, bc); acc.w += sg; lsum += bc;
            sig_bce(x2.x, y.x, sg, bc); acc.x += sg; lsum += bc;
            sig_bce(x2.y, y.y, sg, bc); acc.y += sg; lsum += bc;
            sig_bce(x2.z, y.z, sg, bc); acc.z += sg; lsum += bc;
            sig_bce(x2.w, y.w, sg, bc); acc.w += sg; lsum += bc;
            sig_bce(x3.x, y.x, sg, bc); acc.x += sg; lsum += bc;
            sig_bce(x3.y, y.y, sg, bc); acc.y += sg; lsum += bc;
            sig_bce(x3.z, y.z, sg, bc); acc.z += sg; lsum += bc;
            sig_bce(x3.w, y.w, sg, bc); acc.w += sg; lsum += bc;
        }
        for (; i < n; ++i) {
            const int r0 = (i < SROWS) ? s_rows[i] : g_sorted[s + i];
            const float4 x0 = ldcs4((const float4*)(dense_out + (size_t)r0 * DD) + col4);
            sig_bce(x0.x, y.x, sg, bc); acc.x += sg; lsum += bc;
            sig_bce(x0.y, y.y, sg, bc); acc.y += sg; lsum += bc;
            sig_bce(x0.z, y.z, sg, bc); acc.z += sg; lsum += bc;
            sig_bce(x0.w, y.w, sg, bc); acc.w += sg; lsum += bc;
        }

        float* dst = out_ds + (size_t)c * DD + (size_t)col4 * 4;  // 4B-aligned
        stcs(dst + 0, acc.x); stcs(dst + 1, acc.y);
        stcs(dst + 2, acc.z); stcs(dst + 3, acc.w);

        #pragma unroll
        for (int o = 16; o; o >>= 1)
            lsum += __shfl_xor_sync(0xffffffffu, lsum, o);
        __shared__ float wpart[8];
        const int wid = threadIdx.x >> 5, lane = threadIdx.x & 31;
        if (lane == 0) wpart[wid] = lsum;
        __syncthreads();
        if (threadIdx.x == 0) {
            float bs = 0.f;
            #pragma unroll
            for (int w = 0; w < 8; ++w) bs += wpart[w];
            atomicAdd(&g_loss2, (double)bs);
        }

    } else {
        // ==================== CROSS-ENTROPY ====================
        const int warp = threadIdx.x >> 5;
        const int lane = threadIdx.x & 31;
        const int r    = (blockIdx.x - DENSE_BLOCKS) * 8 + warp;
        const float4* row = (const float4*)(logits + (size_t)r * NUM_CLASSES);

        float m = -1e30f, ssum = 0.f;
        #pragma unroll
        for (int k = 0; k < 8; ++k) {
            const int idx = k * 32 + lane;           // float4 index, 250 valid
            if (idx < NUM_CLASSES / 4) {
                const float4 v = ldcs4(row + idx);
                const float mv = fmaxf(fmaxf(v.x, v.y), fmaxf(v.z, v.w));
                const float mn = fmaxf(m, mv);
                ssum = ssum * __expf(m - mn)
                     + __expf(v.x - mn) + __expf(v.y - mn)
                     + __expf(v.z - mn) + __expf(v.w - mn);
                m = mn;
            }
        }
        #pragma unroll
        for (int off = 16; off; off >>= 1) {
            const float mo = __shfl_xor_sync(0xffffffffu, m, off);
            const float so = __shfl_xor_sync(0xffffffffu, ssum, off);
            const float mn = fmaxf(m, mo);
            ssum = ssum * __expf(m - mn) + so * __expf(mo - mn);
            m = mn;
        }

        __shared__ float part[8];
        if (lane == 0)
            part[warp] = (__logf(ssum) + m)
                       - logits[(size_t)r * NUM_CLASSES + target[r]];
        __syncthreads();
        if (threadIdx.x == 0) {
            float bs = 0.f;
            #pragma unroll
            for (int w = 0; w < 8; ++w) bs += part[w];
            atomicAdd(&g_loss1, (double)bs);
        }
    }

    // --------------- last-block finalize (replaces final launch) ---------------
    if (threadIdx.x == 0) {
        __threadfence();
        const unsigned int ticket = atomicAdd(&g_done, 1u);
        if (ticket == TOTAL_BLOCKS - 1) {
            __threadfence();
            const double l1 = g_loss1 / (double)BATCH;
            const double l2 = g_loss2 / ((double)BATCH * (double)DD);
            out[0] = (float)(0.5 * l1 + 0.5 * l2);
            g_done = 0u;                    // reset for next graph replay
            g_loss1 = 0.0;
            g_loss2 = 0.0;
        }
    }
}

// ---------------------------------------------------------------------------
extern "C" void kernel_launch(void* const* d_in, const int* in_sizes, int n_in,
                              void* d_out, int out_size) {
    const float* logits       = (const float*)d_in[0];
    const float* dense_out    = (const float*)d_in[1];
    const int*   target       = (const int*)  d_in[2];
    const float* dense_labels = (const float*)d_in[3];

    float* out    = (float*)d_out;
    float* out_ta = out + 1 + (size_t)NUM_CLASSES * DD;

    prep_kernel<<<1, 1024>>>(target, out_ta);
    main_kernel<<<TOTAL_BLOCKS, 256>>>(logits, target, dense_out,
                                       dense_labels, out);
}